// round 2
// baseline (speedup 1.0000x reference)
#include <cuda_runtime.h>

// Problem constants
#define Bn 64
#define Cc 64
#define Hh 32
#define Ww 32
#define Kk 512
#define NN 65536      // B*H*W
#define HWsz 1024     // H*W

// Output layout (float32, concatenated in reference return order)
#define OFF_Q     0u
#define OFF_LOSS  4194304u
#define OFF_PERP  4194368u
#define OFF_ENC   4194369u
#define OFF_EIDX  37748801u
#define OFF_DIST  37814337u

// Scratch (allocation-free: __device__ globals)
__device__ float        g_ee[Kk];
__device__ float        g_loss[Bn];
__device__ unsigned int g_cnt[Kk];

// ---------------------------------------------------------------------------
// Kernel 1: per-launch init — codebook squared norms, zero accumulators.
// 1 block, 512 threads.
// ---------------------------------------------------------------------------
__global__ void k_init(const float* __restrict__ w) {
    int t = threadIdx.x;              // 0..511 == codebook index
    const float4* w4 = (const float4*)w;
    float s = 0.f;
#pragma unroll
    for (int q = 0; q < Cc / 4; q++) {
        float4 v = w4[t * (Cc / 4) + q];
        s += v.x * v.x + v.y * v.y + v.z * v.z + v.w * v.w;
    }
    g_ee[t] = s;
    g_cnt[t] = 0u;
    if (t < Bn) g_loss[t] = 0.f;
}

// ---------------------------------------------------------------------------
// Kernel 2: main. Each block: 32 rows x all 512 codes.
// 256 threads = 8 (ty, row groups of 4) x 32 (tx, k groups of 16).
// C tiled by 16 (4 tiles). Per-thread 4x16 fp32 accumulators.
// ---------------------------------------------------------------------------
__global__ __launch_bounds__(256) void k_main(const float* __restrict__ x,
                                              const float* __restrict__ w,
                                              float* __restrict__ out) {
    __shared__ float w_sh[16][Kk];    // 32 KB
    __shared__ float x_sh[16][32];    // 2 KB
    __shared__ float ee_sh[Kk];       // 2 KB
    __shared__ float xx_sh[32];
    __shared__ int   idx_sh[32];

    const int t  = threadIdx.x;
    const int tx = t & 31;
    const int ty = t >> 5;
    const int n0  = blockIdx.x << 5;       // first row of this block
    const int bb  = n0 >> 10;              // batch index (HW=1024 divides 32-row tiles)
    const int hw0 = n0 & 1023;

    ee_sh[t]       = g_ee[t];
    ee_sh[t + 256] = g_ee[t + 256];

    float acc[4][16];
#pragma unroll
    for (int i = 0; i < 4; i++)
#pragma unroll
        for (int j = 0; j < 16; j++) acc[i][j] = 0.f;

    float xxacc = 0.f;
    const float*  xb = x + (size_t)bb * Cc * HWsz + hw0;
    const float4* w4 = (const float4*)w;

    for (int ct = 0; ct < 4; ct++) {
        // x tile: x_sh[cl][nl] = x[n0+nl][ct*16+cl]  (coalesced 128B rows)
#pragma unroll
        for (int u = t; u < 512; u += 256) {
            int cl = u >> 5, nl = u & 31;
            x_sh[cl][nl] = xb[(size_t)(ct * 16 + cl) * HWsz + nl];
        }
        // w tile: w_sh[cl][k] = w[k][ct*16+cl]  (float4 along C)
#pragma unroll
        for (int u = t; u < 2048; u += 256) {
            int k = u >> 2, c4 = u & 3;
            float4 v = w4[k * (Cc / 4) + ct * 4 + c4];
            w_sh[c4 * 4 + 0][k] = v.x;
            w_sh[c4 * 4 + 1][k] = v.y;
            w_sh[c4 * 4 + 2][k] = v.z;
            w_sh[c4 * 4 + 3][k] = v.w;
        }
        __syncthreads();

        if (t < 32) {
#pragma unroll
            for (int cl = 0; cl < 16; cl++) {
                float v = x_sh[cl][t];
                xxacc = fmaf(v, v, xxacc);
            }
        }

#pragma unroll
        for (int c = 0; c < 16; c++) {
            float a[4], bw[16];
#pragma unroll
            for (int i = 0; i < 4; i++) a[i] = x_sh[c][ty * 4 + i];
#pragma unroll
            for (int j = 0; j < 16; j++) bw[j] = w_sh[c][tx + 32 * j];
#pragma unroll
            for (int i = 0; i < 4; i++)
#pragma unroll
                for (int j = 0; j < 16; j++)
                    acc[i][j] = fmaf(a[i], bw[j], acc[i][j]);
        }
        __syncthreads();
    }

    if (t < 32) xx_sh[t] = xxacc;
    __syncthreads();

    float* dist_base = out + OFF_DIST;
    float* enc_base  = out + OFF_ENC;

#pragma unroll
    for (int i = 0; i < 4; i++) {
        const int r = ty * 4 + i;
        const int n = n0 + r;
        const float xxr = xx_sh[r];
        const size_t rowoff = (size_t)n * Kk;

        float bd = 3.4e38f;
        int   bk = 0;
#pragma unroll
        for (int j = 0; j < 16; j++) {
            int k = tx + 32 * j;
            float d = xxr + ee_sh[k] - 2.f * acc[i][j];
            dist_base[rowoff + k] = d;
            if (d < bd) { bd = d; bk = k; }   // strict < keeps first (lowest k)
        }
        // warp argmin, lexicographic tie-break to lowest k (jnp.argmin semantics)
#pragma unroll
        for (int off = 16; off > 0; off >>= 1) {
            float od = __shfl_down_sync(0xffffffffu, bd, off);
            int   ok = __shfl_down_sync(0xffffffffu, bk, off);
            if (od < bd || (od == bd && ok < bk)) { bd = od; bk = ok; }
        }
        bk = __shfl_sync(0xffffffffu, bk, 0);
        bd = __shfl_sync(0xffffffffu, bd, 0);

        if (tx == 0) {
            idx_sh[r] = bk;
            atomicAdd(&g_cnt[bk], 1u);
            atomicAdd(&g_loss[bb], bd);       // min-dist == ||x - w_k||^2
            out[OFF_EIDX + n] = (float)bk;
        }
        // one-hot encodings row
#pragma unroll
        for (int j = 0; j < 16; j++) {
            int k = tx + 32 * j;
            enc_base[rowoff + k] = (k == bk) ? 1.f : 0.f;
        }
    }
    __syncthreads();

    // q_out (NCHW): out[b][c][hw0+nl] = w[idx[nl]][c]  — coalesced over nl
#pragma unroll
    for (int it = 0; it < 8; it++) {
        int u  = t + 256 * it;
        int cl = u >> 5, nl = u & 31;
        out[OFF_Q + (size_t)bb * Cc * HWsz + (size_t)cl * HWsz + hw0 + nl] =
            w[idx_sh[nl] * Cc + cl];
    }
}

// ---------------------------------------------------------------------------
// Kernel 3: finalize — perplexity + loss scaling. 1 block, 512 threads.
// ---------------------------------------------------------------------------
__global__ void k_final(float* __restrict__ out) {
    __shared__ float red[Kk];
    int t = threadIdx.x;
    float p = (float)g_cnt[t] * (1.f / (float)NN);
    red[t] = p * logf(p + 1e-10f);    // p==0 -> 0 * log(1e-10) == 0, matches ref
    __syncthreads();
    for (int s = 256; s > 0; s >>= 1) {
        if (t < s) red[t] += red[t + s];
        __syncthreads();
    }
    if (t == 0) out[OFF_PERP] = expf(-red[0]);
    // loss = q_latent + 0.25*e_latent = 1.25 * mean((q - x)^2) over H*W*C
    if (t < Bn) out[OFF_LOSS + t] = g_loss[t] * (1.25f / 65536.f);
}

// ---------------------------------------------------------------------------
extern "C" void kernel_launch(void* const* d_in, const int* in_sizes, int n_in,
                              void* d_out, int out_size) {
    const float* x = (const float*)d_in[0];   // inputs [B,C,H,W]
    const float* w = (const float*)d_in[1];   // weight [K,C]
    float* out = (float*)d_out;

    k_init<<<1, 512>>>(w);
    k_main<<<NN / 32, 256>>>(x, w, out);
    k_final<<<1, 512>>>(out);
}

// round 7
// speedup vs baseline: 1.0167x; 1.0167x over previous
#include <cuda_runtime.h>
#include <cuda_bf16.h>
#include <cstdint>

// ---------------- output layout (float32 concat, reference return order) ---
#define OFF_Q     0u
#define OFF_LOSS  4194304u
#define OFF_PERP  4194368u
#define OFF_ENC   4194369u
#define OFF_EIDX  37748801u
#define OFF_DIST  37814337u

// ---------------- dynamic SMEM layout (bytes) ------------------------------
#define PB 144                         // 72 bf16 pitch: ldmatrix conflict-free
#define S_WHI  0                       // 512 x 72 bf16 hi       73728
#define S_WLO  (S_WHI + 512 * PB)      // 512 x 72 bf16 lo       73728
#define S_XHI  (S_WLO + 512 * PB)      // 128 x 72 bf16 hi       18432
#define S_XLO  (S_XHI + 128 * PB)      // 128 x 72 bf16 lo       18432
#define S_EE   (S_XLO + 128 * PB)      // 512 f32                 2048
#define S_XXP  (S_EE + 2048)           // 2 x 128 f32             1024
#define S_IDX  (S_XXP + 1024)          // 128 int                  512
#define S_LRED (S_IDX + 512)           // 8 f32                     32
#define S_STG  (S_LRED + 32)           // 8 warps x 16 x 66 f32  33792
#define S_TOTAL (S_STG + 33792)        // 221728  (< 227 KB)

// ---------------- scratch (allocation-free) --------------------------------
__device__ float g_lossp[512];         // per-CTA loss partials, rewritten each launch

// ---------------- asm helpers ----------------------------------------------
__device__ __forceinline__ uint32_t smem_u32(const void* p) {
    uint32_t a;
    asm("{ .reg .u64 t; cvta.to.shared.u64 t, %1; cvt.u32.u64 %0, t; }" : "=r"(a) : "l"(p));
    return a;
}
#define LDSM_X4(r, a)                                                          \
    asm volatile("ldmatrix.sync.aligned.m8n8.x4.shared.b16 {%0,%1,%2,%3}, [%4];" \
        : "=r"((r)[0]), "=r"((r)[1]), "=r"((r)[2]), "=r"((r)[3]) : "r"(a))

#define MMA16816(d, a, b)                                                      \
    asm volatile("mma.sync.aligned.m16n8k16.row.col.f32.bf16.bf16.f32 "        \
        "{%0,%1,%2,%3}, {%4,%5,%6,%7}, {%8,%9}, {%0,%1,%2,%3};"                \
        : "+f"((d)[0]), "+f"((d)[1]), "+f"((d)[2]), "+f"((d)[3])               \
        : "r"((a)[0]), "r"((a)[1]), "r"((a)[2]), "r"((a)[3]),                  \
          "r"((b)[0]), "r"((b)[1]))

__device__ __forceinline__ unsigned short f2bf(float v) {
    __nv_bfloat16 b = __float2bfloat16_rn(v);
    return *reinterpret_cast<unsigned short*>(&b);
}
__device__ __forceinline__ float bf2f(unsigned short u) {
    __nv_bfloat16 b = *reinterpret_cast<__nv_bfloat16*>(&u);
    return __bfloat162float(b);
}
__device__ __forceinline__ uint32_t pack_hi(float a, float b) {
    return (uint32_t)f2bf(a) | ((uint32_t)f2bf(b) << 16);
}
__device__ __forceinline__ uint32_t pack_lo(float a, float b) {
    return (uint32_t)f2bf(a - bf2f(f2bf(a))) | ((uint32_t)f2bf(b - bf2f(f2bf(b))) << 16);
}

__device__ __forceinline__ void top2_upd(float d, int k, float& d1, int& k1,
                                         float& d2, int& k2) {
    if (d < d1)      { d2 = d1; k2 = k1; d1 = d; k1 = k; }
    else if (d < d2) { d2 = d; k2 = k; }
}
__device__ __forceinline__ void top2_merge(float e1, int j1, float e2, int j2,
                                           float& d1, int& k1, float& d2, int& k2) {
    if (e1 < d1 || (e1 == d1 && j1 < k1)) {
        if (d1 < e2 || (d1 == e2 && k1 < j2)) { d2 = d1; k2 = k1; }
        else                                  { d2 = e2; k2 = j2; }
        d1 = e1; k1 = j1;
    } else if (e1 < d2 || (e1 == d2 && j1 < k2)) {
        d2 = e1; k2 = j1;
    }
}
__device__ __forceinline__ float dot_exact(const float* xr, const float* wr) {
    float s = 0.f;
#pragma unroll
    for (int c = 0; c < 64; ++c) s = fmaf(xr[(size_t)c * 1024], wr[c], s);
    return s;
}

// ===========================================================================
// Main: 512 CTAs x 256 thr. Each CTA: 128 rows x 512 codes via HMMA (bf16
// hi/lo split, 3 passes, fp32 accum) + top-2 argmin with exact fp32 fixup.
// ===========================================================================
__global__ void __launch_bounds__(256, 1)
k_main(const float* __restrict__ x, const float* __restrict__ w,
       float* __restrict__ out) {
    extern __shared__ char sm[];
    const uint32_t su = smem_u32(sm);
    const int t    = threadIdx.x;
    const int lane = t & 31;
    const int wid  = t >> 5;
    const int n0   = blockIdx.x << 7;     // 128 rows / CTA
    const int bb   = n0 >> 10;            // batch
    const int hw0  = n0 & 1023;

    // ---- x tile: fp32 -> bf16 hi/lo (pitched, ldmatrix-ready); ||x||^2 ----
    {
        const int hwl = t & 127, ch = t >> 7;
        const float* xg = x + (size_t)bb * 65536 + hw0 + hwl;
        float xxa = 0.f;
#pragma unroll
        for (int cc = 0; cc < 32; cc += 2) {
            const int c = ch * 32 + cc;
            float v0 = xg[(size_t)c * 1024];
            float v1 = xg[(size_t)(c + 1) * 1024];
            xxa = fmaf(v0, v0, fmaf(v1, v1, xxa));
            *(uint32_t*)(sm + S_XHI + hwl * PB + c * 2) = pack_hi(v0, v1);
            *(uint32_t*)(sm + S_XLO + hwl * PB + c * 2) = pack_lo(v0, v1);
        }
        ((float*)(sm + S_XXP))[ch * 128 + hwl] = xxa;
    }

    // ---- w: fp32 -> bf16 hi/lo pitched; ee[k] = ||w_k||^2 -----------------
    {
        const float4* w4 = (const float4*)w;
#pragma unroll
        for (int it = 0; it < 32; ++it) {
            const int u = t + 256 * it;
            const int k = u >> 4, j = u & 15;          // 16 threads per code
            float4 v = w4[(size_t)k * 16 + j];
            float s = v.x * v.x + v.y * v.y + v.z * v.z + v.w * v.w;
            s += __shfl_xor_sync(0xffffffffu, s, 8);
            s += __shfl_xor_sync(0xffffffffu, s, 4);
            s += __shfl_xor_sync(0xffffffffu, s, 2);
            s += __shfl_xor_sync(0xffffffffu, s, 1);
            if ((t & 15) == 0) ((float*)(sm + S_EE))[k] = s;
            *(uint2*)(sm + S_WHI + k * PB + j * 8) =
                make_uint2(pack_hi(v.x, v.y), pack_hi(v.z, v.w));
            *(uint2*)(sm + S_WLO + k * PB + j * 8) =
                make_uint2(pack_lo(v.x, v.y), pack_lo(v.z, v.w));
        }
    }
    __syncthreads();

    // ---- per-warp MMA over 16 rows x 512 codes ----------------------------
    const int r0 = wid * 16;
    const int l7 = lane & 7, seg = lane >> 3, t4 = lane & 3, g = lane >> 2;

    // A fragments (resident): 4 k-steps x 4 regs, hi + lo
    const uint32_t aoff = (uint32_t)(r0 + l7 + ((seg & 1) << 3)) * PB + ((seg >> 1) << 4);
    uint32_t AH[4][4], AL[4][4];
#pragma unroll
    for (int kk = 0; kk < 4; ++kk) {
        LDSM_X4(AH[kk], su + S_XHI + aoff + kk * 32);
        LDSM_X4(AL[kk], su + S_XLO + aoff + kk * 32);
    }
    const uint32_t boff = (uint32_t)(l7 + ((seg >> 1) << 3)) * PB + ((seg & 1) << 4);

    const float* xxp = (const float*)(sm + S_XXP);
    const float xg0 = xxp[r0 + g]     + xxp[128 + r0 + g];
    const float xg8 = xxp[r0 + g + 8] + xxp[128 + r0 + g + 8];
    const float* ee = (const float*)(sm + S_EE);
    float* stg = (float*)(sm + S_STG) + wid * (16 * 66);

    float d1a = 3.4e38f, d2a = 3.4e38f, d1b = 3.4e38f, d2b = 3.4e38f;
    int   k1a = 0, k2a = 0, k1b = 0, k2b = 0;

    for (int nc = 0; nc < 8; ++nc) {
        float acc[8][4];
#pragma unroll
        for (int q = 0; q < 8; ++q)
#pragma unroll
            for (int r = 0; r < 4; ++r) acc[q][r] = 0.f;

        const uint32_t wbh = su + S_WHI + nc * 64 * PB + boff;
        const uint32_t wbl = su + S_WLO + nc * 64 * PB + boff;
#pragma unroll
        for (int p = 0; p < 4; ++p)
#pragma unroll
            for (int kk = 0; kk < 4; ++kk) {
                uint32_t BH[4], BL[4];
                LDSM_X4(BH, wbh + p * 16 * PB + kk * 32);
                LDSM_X4(BL, wbl + p * 16 * PB + kk * 32);
                MMA16816(acc[2 * p],     AH[kk], BH);
                MMA16816(acc[2 * p + 1], AH[kk], BH + 2);
                MMA16816(acc[2 * p],     AH[kk], BL);
                MMA16816(acc[2 * p + 1], AH[kk], BL + 2);
                MMA16816(acc[2 * p],     AL[kk], BH);
                MMA16816(acc[2 * p + 1], AL[kk], BH + 2);
            }

        // distances for this 16x64 tile -> top2 + SMEM stage
#pragma unroll
        for (int nt = 0; nt < 8; ++nt) {
            const int kloc = nt * 8 + 2 * t4;
            const int kg   = nc * 64 + kloc;
            const float2 eev = *(const float2*)(ee + kg);
            const float D0 = xg0 + eev.x - 2.f * acc[nt][0];
            const float D1 = xg0 + eev.y - 2.f * acc[nt][1];
            const float D2 = xg8 + eev.x - 2.f * acc[nt][2];
            const float D3 = xg8 + eev.y - 2.f * acc[nt][3];
            top2_upd(D0, kg,     d1a, k1a, d2a, k2a);
            top2_upd(D1, kg + 1, d1a, k1a, d2a, k2a);
            top2_upd(D2, kg,     d1b, k1b, d2b, k2b);
            top2_upd(D3, kg + 1, d1b, k1b, d2b, k2b);
            *(float2*)(stg + g * 66 + kloc)       = make_float2(D0, D1);
            *(float2*)(stg + (g + 8) * 66 + kloc) = make_float2(D2, D3);
        }
        __syncwarp();

        // aligned burst write of this chunk (row base global idx == 1 mod 4)
        {
            const int row = lane >> 1, part = lane & 1;
            float* gp = out + OFF_DIST + (size_t)(n0 + r0 + row) * 512 + nc * 64;
            const float* sp = stg + row * 66;
            if (part == 0) {
                gp[0] = sp[0]; gp[1] = sp[1]; gp[2] = sp[2];
#pragma unroll
                for (int j = 0; j < 7; ++j) {
                    const int o = 3 + 4 * j;
                    *(float4*)(gp + o) = make_float4(sp[o], sp[o+1], sp[o+2], sp[o+3]);
                }
            } else {
#pragma unroll
                for (int j = 0; j < 8; ++j) {
                    const int o = 31 + 4 * j;
                    *(float4*)(gp + o) = make_float4(sp[o], sp[o+1], sp[o+2], sp[o+3]);
                }
                gp[63] = sp[63];
            }
        }
        __syncwarp();
    }

    // ---- merge top2 across the 4 lanes of each row ------------------------
#pragma unroll
    for (int m = 1; m <= 2; m <<= 1) {
        float e1 = __shfl_xor_sync(0xffffffffu, d1a, m);
        int   j1 = __shfl_xor_sync(0xffffffffu, k1a, m);
        float e2 = __shfl_xor_sync(0xffffffffu, d2a, m);
        int   j2 = __shfl_xor_sync(0xffffffffu, k2a, m);
        top2_merge(e1, j1, e2, j2, d1a, k1a, d2a, k2a);
        e1 = __shfl_xor_sync(0xffffffffu, d1b, m);
        j1 = __shfl_xor_sync(0xffffffffu, k1b, m);
        e2 = __shfl_xor_sync(0xffffffffu, d2b, m);
        j2 = __shfl_xor_sync(0xffffffffu, k2b, m);
        top2_merge(e1, j1, e2, j2, d1b, k1b, d2b, k2b);
    }

    // ---- exact fp32 fixup when the top-2 gap is within MMA error margin ---
    if (t4 == 0) {
        const float TAU = 1e-4f;
        const int rA = r0 + g, rB = rA + 8;
        if (d2a - d1a < TAU) {
            const float* xr = x + (size_t)bb * 65536 + hw0 + rA;
            const float DA = xg0 + ee[k1a] - 2.f * dot_exact(xr, w + (size_t)k1a * 64);
            const float DB = xg0 + ee[k2a] - 2.f * dot_exact(xr, w + (size_t)k2a * 64);
            if (DB < DA || (DB == DA && k2a < k1a)) { k1a = k2a; d1a = DB; }
            else d1a = DA;
        }
        if (d2b - d1b < TAU) {
            const float* xr = x + (size_t)bb * 65536 + hw0 + rB;
            const float DA = xg8 + ee[k1b] - 2.f * dot_exact(xr, w + (size_t)k1b * 64);
            const float DB = xg8 + ee[k2b] - 2.f * dot_exact(xr, w + (size_t)k2b * 64);
            if (DB < DA || (DB == DA && k2b < k1b)) { k1b = k2b; d1b = DB; }
            else d1b = DA;
        }
        ((int*)(sm + S_IDX))[rA] = k1a;
        ((int*)(sm + S_IDX))[rB] = k1b;
        out[OFF_EIDX + n0 + rA] = (float)k1a;
        out[OFF_EIDX + n0 + rB] = (float)k1b;
    }
    __syncwarp();

    // ---- encodings: full one-hot rows, aligned bursts (no memset pass) ----
    {
        const int er  = r0 + (lane >> 1);               // this warp's 16 rows
        const int ebk = ((const int*)(sm + S_IDX))[er];
        float* ep = out + OFF_ENC + (size_t)(n0 + er) * 512;
        if ((lane & 1) == 0) {
            ep[0] = (0 == ebk); ep[1] = (1 == ebk); ep[2] = (2 == ebk);
#pragma unroll 9
            for (int j = 0; j < 63; ++j) {
                const int o = 3 + 4 * j;
                *(float4*)(ep + o) = make_float4(o == ebk, o + 1 == ebk,
                                                 o + 2 == ebk, o + 3 == ebk);
            }
        } else {
#pragma unroll 8
            for (int j = 0; j < 64; ++j) {
                const int o = 255 + 4 * j;
                *(float4*)(ep + o) = make_float4(o == ebk, o + 1 == ebk,
                                                 o + 2 == ebk, o + 3 == ebk);
            }
            ep[511] = (511 == ebk);
        }
    }

    // ---- loss partial -----------------------------------------------------
    float ls = (t4 == 0) ? (d1a + d1b) : 0.f;
#pragma unroll
    for (int off = 16; off > 0; off >>= 1) ls += __shfl_down_sync(0xffffffffu, ls, off);
    if (lane == 0) ((float*)(sm + S_LRED))[wid] = ls;
    __syncthreads();
    if (t == 0) {
        const float* lr = (const float*)(sm + S_LRED);
        g_lossp[blockIdx.x] = lr[0] + lr[1] + lr[2] + lr[3] +
                              lr[4] + lr[5] + lr[6] + lr[7];
    }

    // ---- q_out via SMEM transpose staging (reuses stage region) -----------
    float* qs = (float*)(sm + S_STG);
    const int* idxs = (const int*)(sm + S_IDX);
    for (int rr = wid; rr < 128; rr += 8) {
        const float* wr = w + (size_t)idxs[rr] * 64;
        qs[rr * 66 + lane]      = wr[lane];
        qs[rr * 66 + 32 + lane] = wr[32 + lane];
    }
    __syncthreads();
    float* qb = out + OFF_Q + (size_t)bb * 65536 + hw0;
#pragma unroll
    for (int i2 = 0; i2 < 32; ++i2) {
        const int u = t + 256 * i2;
        const int c = u >> 7, hl = u & 127;
        qb[(size_t)c * 1024 + hl] = qs[hl * 66 + c];
    }
}

// ===========================================================================
// Finalize: histogram from enc_idx -> perplexity; loss from partials
// ===========================================================================
__global__ void k_final(float* __restrict__ out) {
    __shared__ unsigned int hist[512];
    __shared__ float red[512];
    const int t = threadIdx.x;   // 1024 threads
    if (t < 512) hist[t] = 0u;
    __syncthreads();
    const float* ei = out + OFF_EIDX;
#pragma unroll 4
    for (int i = t; i < 65536; i += 1024)
        atomicAdd(&hist[(int)ei[i]], 1u);
    __syncthreads();
    if (t < 512) {
        const float p = (float)hist[t] * (1.f / 65536.f);
        red[t] = p * logf(p + 1e-10f);
    }
    __syncthreads();
    for (int s = 256; s > 0; s >>= 1) {
        if (t < s) red[t] += red[t + s];
        __syncthreads();
    }
    if (t == 0) out[OFF_PERP] = expf(-red[0]);
    if (t < 64) {
        float s = 0.f;
#pragma unroll
        for (int j = 0; j < 8; ++j) s += g_lossp[t * 8 + j];
        out[OFF_LOSS + t] = s * (1.25f / 65536.f);
    }
}

// ===========================================================================
extern "C" void kernel_launch(void* const* d_in, const int* in_sizes, int n_in,
                              void* d_out, int out_size) {
    const float* x = (const float*)d_in[0];
    const float* w = (const float*)d_in[1];
    float* out = (float*)d_out;

    cudaFuncSetAttribute(k_main, cudaFuncAttributeMaxDynamicSharedMemorySize, S_TOTAL);
    k_main<<<512, 256, S_TOTAL>>>(x, w, out);
    k_final<<<1, 1024>>>(out);
}

// round 8
// speedup vs baseline: 1.4071x; 1.3840x over previous
#include <cuda_runtime.h>
#include <cuda_bf16.h>
#include <cstdint>

// ---------------- output layout (float32 concat, reference return order) ---
#define OFF_Q     0u
#define OFF_LOSS  4194304u
#define OFF_PERP  4194368u
#define OFF_ENC   4194369u
#define OFF_EIDX  37748801u
#define OFF_DIST  37814337u

// ---------------- dynamic SMEM layout (bytes) ------------------------------
#define PB 144                         // 72 bf16 pitch: ldmatrix conflict-free
#define S_WHI  0                       // 512 x 72 bf16 hi       73728
#define S_WLO  (S_WHI + 512 * PB)      // 512 x 72 bf16 lo       73728
#define S_XHI  (S_WLO + 512 * PB)      // 128 x 72 bf16 hi       18432
#define S_XLO  (S_XHI + 128 * PB)      // 128 x 72 bf16 lo       18432
#define S_EE   (S_XLO + 128 * PB)      // 512 f32                 2048
#define S_XXP  (S_EE + 2048)           // 2 x 128 f32             1024
#define S_IDX  (S_XXP + 1024)          // 128 int                  512
#define S_LRED (S_IDX + 512)           // 8 f32                     32
#define S_STG  (S_LRED + 32)           // 8 warps x 16 x 66 f32  33792
#define S_TOTAL (S_STG + 33792)        // 221728  (< 227 KB)

// ---------------- scratch (allocation-free, self-resetting) ----------------
__device__ unsigned int        g_cnt[512];     // histogram (zero-init; last CTA resets)
__device__ unsigned long long  g_loss_i[64];   // fixed-point loss partials
__device__ unsigned int        g_tick;         // CTA completion ticket

// ---------------- asm helpers ----------------------------------------------
__device__ __forceinline__ uint32_t smem_u32(const void* p) {
    uint32_t a;
    asm("{ .reg .u64 t; cvta.to.shared.u64 t, %1; cvt.u32.u64 %0, t; }" : "=r"(a) : "l"(p));
    return a;
}
#define LDSM_X4(r, a)                                                          \
    asm volatile("ldmatrix.sync.aligned.m8n8.x4.shared.b16 {%0,%1,%2,%3}, [%4];" \
        : "=r"((r)[0]), "=r"((r)[1]), "=r"((r)[2]), "=r"((r)[3]) : "r"(a))

#define MMA16816(d, a, b)                                                      \
    asm volatile("mma.sync.aligned.m16n8k16.row.col.f32.bf16.bf16.f32 "        \
        "{%0,%1,%2,%3}, {%4,%5,%6,%7}, {%8,%9}, {%0,%1,%2,%3};"                \
        : "+f"((d)[0]), "+f"((d)[1]), "+f"((d)[2]), "+f"((d)[3])               \
        : "r"((a)[0]), "r"((a)[1]), "r"((a)[2]), "r"((a)[3]),                  \
          "r"((b)[0]), "r"((b)[1]))

__device__ __forceinline__ unsigned short f2bf(float v) {
    __nv_bfloat16 b = __float2bfloat16_rn(v);
    return *reinterpret_cast<unsigned short*>(&b);
}
__device__ __forceinline__ float bf2f(unsigned short u) {
    __nv_bfloat16 b = *reinterpret_cast<__nv_bfloat16*>(&u);
    return __bfloat162float(b);
}
__device__ __forceinline__ uint32_t pack_hi(float a, float b) {
    return (uint32_t)f2bf(a) | ((uint32_t)f2bf(b) << 16);
}
__device__ __forceinline__ uint32_t pack_lo(float a, float b) {
    return (uint32_t)f2bf(a - bf2f(f2bf(a))) | ((uint32_t)f2bf(b - bf2f(f2bf(b))) << 16);
}

__device__ __forceinline__ void top2_upd(float d, int k, float& d1, int& k1,
                                         float& d2, int& k2) {
    if (d < d1)      { d2 = d1; k2 = k1; d1 = d; k1 = k; }
    else if (d < d2) { d2 = d; k2 = k; }
}
__device__ __forceinline__ void top2_merge(float e1, int j1, float e2, int j2,
                                           float& d1, int& k1, float& d2, int& k2) {
    if (e1 < d1 || (e1 == d1 && j1 < k1)) {
        if (d1 < e2 || (d1 == e2 && k1 < j2)) { d2 = d1; k2 = k1; }
        else                                  { d2 = e2; k2 = j2; }
        d1 = e1; k1 = j1;
    } else if (e1 < d2 || (e1 == d2 && j1 < k2)) {
        d2 = e1; k2 = j1;
    }
}
__device__ __forceinline__ float dot_exact(const float* xr, const float* wr) {
    float s = 0.f;
#pragma unroll
    for (int c = 0; c < 64; ++c) s = fmaf(xr[(size_t)c * 1024], wr[c], s);
    return s;
}

// ===========================================================================
// Single fused kernel: 512 CTAs x 256 thr. Each CTA: 128 rows x 512 codes
// via HMMA (bf16 hi/lo 3-pass, fp32 accum) + top-2 argmin + exact fixup.
// Last CTA computes loss/perplexity and resets scratch.
// ===========================================================================
__global__ void __launch_bounds__(256, 1)
k_main(const float* __restrict__ x, const float* __restrict__ w,
       float* __restrict__ out) {
    extern __shared__ char sm[];
    const uint32_t su = smem_u32(sm);
    const int t    = threadIdx.x;
    const int lane = t & 31;
    const int wid  = t >> 5;
    const int n0   = blockIdx.x << 7;     // 128 rows / CTA
    const int bb   = n0 >> 10;            // batch
    const int hw0  = n0 & 1023;

    // ---- x tile: fp32 -> bf16 hi/lo (pitched, ldmatrix-ready); ||x||^2 ----
    {
        const int hwl = t & 127, ch = t >> 7;
        const float* xg = x + (size_t)bb * 65536 + hw0 + hwl;
        float xxa = 0.f;
#pragma unroll
        for (int cc = 0; cc < 32; cc += 2) {
            const int c = ch * 32 + cc;
            float v0 = xg[(size_t)c * 1024];
            float v1 = xg[(size_t)(c + 1) * 1024];
            xxa = fmaf(v0, v0, fmaf(v1, v1, xxa));
            *(uint32_t*)(sm + S_XHI + hwl * PB + c * 2) = pack_hi(v0, v1);
            *(uint32_t*)(sm + S_XLO + hwl * PB + c * 2) = pack_lo(v0, v1);
        }
        ((float*)(sm + S_XXP))[ch * 128 + hwl] = xxa;
    }

    // ---- w: fp32 -> bf16 hi/lo pitched; ee[k] = ||w_k||^2 -----------------
    {
        const float4* w4 = (const float4*)w;
#pragma unroll
        for (int it = 0; it < 32; ++it) {
            const int u = t + 256 * it;
            const int k = u >> 4, j = u & 15;          // 16 threads per code
            float4 v = w4[(size_t)k * 16 + j];
            float s = v.x * v.x + v.y * v.y + v.z * v.z + v.w * v.w;
            s += __shfl_xor_sync(0xffffffffu, s, 8);
            s += __shfl_xor_sync(0xffffffffu, s, 4);
            s += __shfl_xor_sync(0xffffffffu, s, 2);
            s += __shfl_xor_sync(0xffffffffu, s, 1);
            if ((t & 15) == 0) ((float*)(sm + S_EE))[k] = s;
            *(uint2*)(sm + S_WHI + k * PB + j * 8) =
                make_uint2(pack_hi(v.x, v.y), pack_hi(v.z, v.w));
            *(uint2*)(sm + S_WLO + k * PB + j * 8) =
                make_uint2(pack_lo(v.x, v.y), pack_lo(v.z, v.w));
        }
    }
    __syncthreads();

    // ---- per-warp MMA over 16 rows x 512 codes ----------------------------
    const int r0 = wid * 16;
    const int l7 = lane & 7, seg = lane >> 3, t4 = lane & 3, g = lane >> 2;

    const uint32_t aoff = (uint32_t)(r0 + l7 + ((seg & 1) << 3)) * PB + ((seg >> 1) << 4);
    uint32_t AH[4][4], AL[4][4];
#pragma unroll
    for (int kk = 0; kk < 4; ++kk) {
        LDSM_X4(AH[kk], su + S_XHI + aoff + kk * 32);
        LDSM_X4(AL[kk], su + S_XLO + aoff + kk * 32);
    }
    const uint32_t boff = (uint32_t)(l7 + ((seg >> 1) << 3)) * PB + ((seg & 1) << 4);

    const float* xxp = (const float*)(sm + S_XXP);
    const float xg0 = xxp[r0 + g]     + xxp[128 + r0 + g];
    const float xg8 = xxp[r0 + g + 8] + xxp[128 + r0 + g + 8];
    const float* ee = (const float*)(sm + S_EE);
    float* stg = (float*)(sm + S_STG) + wid * (16 * 66);

    float d1a = 3.4e38f, d2a = 3.4e38f, d1b = 3.4e38f, d2b = 3.4e38f;
    int   k1a = 0, k2a = 0, k1b = 0, k2b = 0;

    for (int nc = 0; nc < 8; ++nc) {
        float acc[8][4];
#pragma unroll
        for (int q = 0; q < 8; ++q)
#pragma unroll
            for (int r = 0; r < 4; ++r) acc[q][r] = 0.f;

        const uint32_t wbh = su + S_WHI + nc * 64 * PB + boff;
        const uint32_t wbl = su + S_WLO + nc * 64 * PB + boff;
#pragma unroll
        for (int p = 0; p < 4; ++p)
#pragma unroll
            for (int kk = 0; kk < 4; ++kk) {
                uint32_t BH[4], BL[4];
                LDSM_X4(BH, wbh + p * 16 * PB + kk * 32);
                LDSM_X4(BL, wbl + p * 16 * PB + kk * 32);
                MMA16816(acc[2 * p],     AH[kk], BH);
                MMA16816(acc[2 * p + 1], AH[kk], BH + 2);
                MMA16816(acc[2 * p],     AH[kk], BL);
                MMA16816(acc[2 * p + 1], AH[kk], BL + 2);
                MMA16816(acc[2 * p],     AL[kk], BH);
                MMA16816(acc[2 * p + 1], AL[kk], BH + 2);
            }

        // distances for this 16x64 tile -> top2 + SMEM stage
#pragma unroll
        for (int nt = 0; nt < 8; ++nt) {
            const int kloc = nt * 8 + 2 * t4;
            const int kg   = nc * 64 + kloc;
            const float2 eev = *(const float2*)(ee + kg);
            const float D0 = xg0 + eev.x - 2.f * acc[nt][0];
            const float D1 = xg0 + eev.y - 2.f * acc[nt][1];
            const float D2 = xg8 + eev.x - 2.f * acc[nt][2];
            const float D3 = xg8 + eev.y - 2.f * acc[nt][3];
            top2_upd(D0, kg,     d1a, k1a, d2a, k2a);
            top2_upd(D1, kg + 1, d1a, k1a, d2a, k2a);
            top2_upd(D2, kg,     d1b, k1b, d2b, k2b);
            top2_upd(D3, kg + 1, d1b, k1b, d2b, k2b);
            *(float2*)(stg + g * 66 + kloc)       = make_float2(D0, D1);
            *(float2*)(stg + (g + 8) * 66 + kloc) = make_float2(D2, D3);
        }
        __syncwarp();

        // full-warp coalesced sweep: 32 consecutive floats per STG
        {
            float* gpD = out + OFF_DIST + (size_t)(n0 + r0) * 512 + nc * 64;
#pragma unroll
            for (int i2 = 0; i2 < 32; ++i2) {
                const int row = i2 >> 1, col = ((i2 & 1) << 5) + lane;
                gpD[(size_t)row * 512 + col] = stg[row * 66 + col];
            }
        }
        __syncwarp();
    }

    // ---- merge top2 across the 4 lanes of each row ------------------------
#pragma unroll
    for (int m = 1; m <= 2; m <<= 1) {
        float e1 = __shfl_xor_sync(0xffffffffu, d1a, m);
        int   j1 = __shfl_xor_sync(0xffffffffu, k1a, m);
        float e2 = __shfl_xor_sync(0xffffffffu, d2a, m);
        int   j2 = __shfl_xor_sync(0xffffffffu, k2a, m);
        top2_merge(e1, j1, e2, j2, d1a, k1a, d2a, k2a);
        e1 = __shfl_xor_sync(0xffffffffu, d1b, m);
        j1 = __shfl_xor_sync(0xffffffffu, k1b, m);
        e2 = __shfl_xor_sync(0xffffffffu, d2b, m);
        j2 = __shfl_xor_sync(0xffffffffu, k2b, m);
        top2_merge(e1, j1, e2, j2, d1b, k1b, d2b, k2b);
    }

    // ---- exact fp32 fixup when the top-2 gap is within MMA error margin ---
    if (t4 == 0) {
        const float TAU = 1e-5f;
        const int rA = r0 + g, rB = rA + 8;
        if (d2a - d1a < TAU) {
            const float* xr = x + (size_t)bb * 65536 + hw0 + rA;
            const float DA = xg0 + ee[k1a] - 2.f * dot_exact(xr, w + (size_t)k1a * 64);
            const float DB = xg0 + ee[k2a] - 2.f * dot_exact(xr, w + (size_t)k2a * 64);
            if (DB < DA || (DB == DA && k2a < k1a)) { k1a = k2a; d1a = DB; }
            else d1a = DA;
        }
        if (d2b - d1b < TAU) {
            const float* xr = x + (size_t)bb * 65536 + hw0 + rB;
            const float DA = xg8 + ee[k1b] - 2.f * dot_exact(xr, w + (size_t)k1b * 64);
            const float DB = xg8 + ee[k2b] - 2.f * dot_exact(xr, w + (size_t)k2b * 64);
            if (DB < DA || (DB == DA && k2b < k1b)) { k1b = k2b; d1b = DB; }
            else d1b = DA;
        }
        ((int*)(sm + S_IDX))[rA] = k1a;
        ((int*)(sm + S_IDX))[rB] = k1b;
        out[OFF_EIDX + n0 + rA] = (float)k1a;
        out[OFF_EIDX + n0 + rB] = (float)k1b;
    }
    __syncwarp();

    // ---- encodings: full-warp coalesced one-hot rows ----------------------
    {
        const int* idxs = (const int*)(sm + S_IDX);
        float* epb = out + OFF_ENC + (size_t)(n0 + r0) * 512;
#pragma unroll
        for (int rr = 0; rr < 16; ++rr) {
            const int ebk = idxs[r0 + rr];
            float* ep = epb + (size_t)rr * 512;
#pragma unroll
            for (int i2 = 0; i2 < 16; ++i2) {
                const int col = lane + 32 * i2;
                ep[col] = (col == ebk) ? 1.f : 0.f;
            }
        }
    }

    // ---- loss partial (per-warp reduce -> per-CTA -> integer atomic) ------
    float ls = (t4 == 0) ? (d1a + d1b) : 0.f;
#pragma unroll
    for (int off = 16; off > 0; off >>= 1) ls += __shfl_down_sync(0xffffffffu, ls, off);
    if (lane == 0) ((float*)(sm + S_LRED))[wid] = ls;
    __syncthreads();
    if (t == 0) {
        const float* lr = (const float*)(sm + S_LRED);
        const float ctaLoss = lr[0] + lr[1] + lr[2] + lr[3] +
                              lr[4] + lr[5] + lr[6] + lr[7];
        atomicAdd(&g_loss_i[bb],
                  (unsigned long long)((double)ctaLoss * 65536.0 + 0.5));
    }
    if (t < 128)
        atomicAdd(&g_cnt[((const int*)(sm + S_IDX))[t]], 1u);

    // ---- q_out via SMEM transpose staging (reuses stage region) -----------
    float* qs = (float*)(sm + S_STG);
    const int* idxs = (const int*)(sm + S_IDX);
    for (int rr = wid; rr < 128; rr += 8) {
        const float* wr = w + (size_t)idxs[rr] * 64;
        qs[rr * 66 + lane]      = wr[lane];
        qs[rr * 66 + 32 + lane] = wr[32 + lane];
    }
    __syncthreads();
    float* qb = out + OFF_Q + (size_t)bb * 65536 + hw0;
#pragma unroll
    for (int i2 = 0; i2 < 32; ++i2) {
        const int u = t + 256 * i2;
        const int c = u >> 7, hl = u & 127;
        qb[(size_t)c * 1024 + hl] = qs[hl * 66 + c];
    }

    // ---- last-CTA finalize: perplexity + loss, then reset scratch ---------
    __shared__ unsigned s_last;
    __threadfence();
    __syncthreads();
    if (t == 0) s_last = (atomicAdd(&g_tick, 1u) == 511u) ? 1u : 0u;
    __syncthreads();
    if (s_last) {
        __threadfence();
        const unsigned c0 = *(volatile unsigned*)&g_cnt[t];
        const unsigned c1 = *(volatile unsigned*)&g_cnt[t + 256];
        const float p0 = (float)c0 * (1.f / 65536.f);
        const float p1 = (float)c1 * (1.f / 65536.f);
        float s = p0 * logf(p0 + 1e-10f) + p1 * logf(p1 + 1e-10f);
#pragma unroll
        for (int off = 16; off > 0; off >>= 1) s += __shfl_down_sync(0xffffffffu, s, off);
        float* red = (float*)(sm + S_LRED);
        if (lane == 0) red[wid] = s;
        __syncthreads();
        if (t == 0) {
            const float tot = red[0] + red[1] + red[2] + red[3] +
                              red[4] + red[5] + red[6] + red[7];
            out[OFF_PERP] = expf(-tot);
        }
        if (t < 64) {
            const unsigned long long v = *(volatile unsigned long long*)&g_loss_i[t];
            out[OFF_LOSS + t] = (float)((double)v * (1.25 / (65536.0 * 65536.0)));
            g_loss_i[t] = 0ull;
        }
        g_cnt[t] = 0u;
        g_cnt[t + 256] = 0u;
        if (t == 0) g_tick = 0u;
    }
}

// ===========================================================================
extern "C" void kernel_launch(void* const* d_in, const int* in_sizes, int n_in,
                              void* d_out, int out_size) {
    const float* x = (const float*)d_in[0];
    const float* w = (const float*)d_in[1];
    float* out = (float*)d_out;

    cudaFuncSetAttribute(k_main, cudaFuncAttributeMaxDynamicSharedMemorySize, S_TOTAL);
    k_main<<<512, 256, S_TOTAL>>>(x, w, out);
}

// round 10
// speedup vs baseline: 1.6233x; 1.1536x over previous
#include <cuda_runtime.h>
#include <cuda_bf16.h>
#include <cstdint>

// ---------------- output layout (float32 concat, reference return order) ---
#define OFF_Q     0u
#define OFF_LOSS  4194304u
#define OFF_PERP  4194368u
#define OFF_ENC   4194369u
#define OFF_EIDX  37748801u
#define OFF_DIST  37814337u

// ---------------- dynamic SMEM layout (bytes) ------------------------------
#define PB 144                          // 72 bf16 pitch: ldmatrix conflict-free
#define S_WHI   0                       // 512 x 72 bf16 hi      73728
#define S_WLO   73728                   // 512 x 72 bf16 lo      73728
#define S_XHI   147456                  // 128 x 72 bf16 hi      18432
#define S_XLO   165888                  // 128 x 72 bf16 lo      18432
#define S_EE    184320                  // 512 f32                2048
#define S_XXP   186368                  // 4 x 128 f32            2048
#define S_IDX   188416                  // 128 int                 512
#define S_LRED  188928                  // 16 f32                   64
#define S_CD1   188992                  // [2][128] f32           1024
#define S_CD2   190016                  // [2][128] f32           1024
#define S_CK1   191040                  // [2][128] int           1024
#define S_CK2   192064                  // [2][128] int           1024
#define S_STG   193088                  // 16 warps x 16 x 34 f32 34816
#define S_TOTAL 227904                  // <= 232448
// q_out staging (128 x 66 f32 = 33792 B) reuses S_STG after dist writes.

// ---------------- scratch (allocation-free, self-resetting) ----------------
__device__ unsigned int        g_cnt[512];     // histogram (zero-init; last CTA resets)
__device__ unsigned long long  g_loss_i[64];   // fixed-point loss partials
__device__ unsigned int        g_tick;         // CTA completion ticket

// ---------------- asm helpers ----------------------------------------------
__device__ __forceinline__ uint32_t smem_u32(const void* p) {
    uint32_t a;
    asm("{ .reg .u64 t; cvta.to.shared.u64 t, %1; cvt.u32.u64 %0, t; }" : "=r"(a) : "l"(p));
    return a;
}
#define LDSM_X4(r, a)                                                          \
    asm volatile("ldmatrix.sync.aligned.m8n8.x4.shared.b16 {%0,%1,%2,%3}, [%4];" \
        : "=r"((r)[0]), "=r"((r)[1]), "=r"((r)[2]), "=r"((r)[3]) : "r"(a))

#define MMA16816(d, a, b)                                                      \
    asm volatile("mma.sync.aligned.m16n8k16.row.col.f32.bf16.bf16.f32 "        \
        "{%0,%1,%2,%3}, {%4,%5,%6,%7}, {%8,%9}, {%0,%1,%2,%3};"                \
        : "+f"((d)[0]), "+f"((d)[1]), "+f"((d)[2]), "+f"((d)[3])               \
        : "r"((a)[0]), "r"((a)[1]), "r"((a)[2]), "r"((a)[3]),                  \
          "r"((b)[0]), "r"((b)[1]))

__device__ __forceinline__ unsigned short f2bf(float v) {
    __nv_bfloat16 b = __float2bfloat16_rn(v);
    return *reinterpret_cast<unsigned short*>(&b);
}
__device__ __forceinline__ float bf2f(unsigned short u) {
    __nv_bfloat16 b = *reinterpret_cast<__nv_bfloat16*>(&u);
    return __bfloat162float(b);
}
__device__ __forceinline__ uint32_t pack_hi(float a, float b) {
    return (uint32_t)f2bf(a) | ((uint32_t)f2bf(b) << 16);
}
__device__ __forceinline__ uint32_t pack_lo(float a, float b) {
    return (uint32_t)f2bf(a - bf2f(f2bf(a))) | ((uint32_t)f2bf(b - bf2f(f2bf(b))) << 16);
}

__device__ __forceinline__ void top2_upd(float d, int k, float& d1, int& k1,
                                         float& d2, int& k2) {
    if (d < d1)      { d2 = d1; k2 = k1; d1 = d; k1 = k; }
    else if (d < d2) { d2 = d; k2 = k; }
}
__device__ __forceinline__ void top2_merge(float e1, int j1, float e2, int j2,
                                           float& d1, int& k1, float& d2, int& k2) {
    if (e1 < d1 || (e1 == d1 && j1 < k1)) {
        if (d1 < e2 || (d1 == e2 && k1 < j2)) { d2 = d1; k2 = k1; }
        else                                  { d2 = e2; k2 = j2; }
        d1 = e1; k1 = j1;
    } else if (e1 < d2 || (e1 == d2 && j1 < k2)) {
        d2 = e1; k2 = j1;
    }
}
__device__ __forceinline__ float dot_exact(const float* xr, const float* wr) {
    float s = 0.f;
#pragma unroll
    for (int c = 0; c < 64; ++c) s = fmaf(xr[(size_t)c * 1024], wr[c], s);
    return s;
}

// ===========================================================================
// Fused kernel: 512 CTAs x 512 thr (16 warps). Warp pair (wg) owns 16 rows;
// each warp of the pair covers 256 of the 512 codes. HMMA bf16 hi/lo 3-pass.
// All comparisons in FULL distance domain (||x||^2 included) so the ulp(64)
// quantization — and hence tie structure — matches the fp32 reference.
// ===========================================================================
__global__ void __launch_bounds__(512, 1)
k_main(const float* __restrict__ x, const float* __restrict__ w,
       float* __restrict__ out) {
    extern __shared__ char sm[];
    const uint32_t su = smem_u32(sm);
    const int t    = threadIdx.x;
    const int lane = t & 31;
    const int wid  = t >> 5;
    const int n0   = blockIdx.x << 7;     // 128 rows / CTA
    const int bb   = n0 >> 10;            // batch
    const int hw0  = n0 & 1023;

    // ---- x tile: fp32 -> bf16 hi/lo (pitched); 4-way ||x||^2 partials -----
    {
        const int hwl = t & 127, ch4 = t >> 7;         // ch4: 0..3
        const float* xg = x + (size_t)bb * 65536 + hw0 + hwl;
        float xxa = 0.f;
#pragma unroll
        for (int cc = 0; cc < 16; cc += 2) {
            const int c = ch4 * 16 + cc;
            float v0 = xg[(size_t)c * 1024];
            float v1 = xg[(size_t)(c + 1) * 1024];
            xxa = fmaf(v0, v0, fmaf(v1, v1, xxa));
            *(uint32_t*)(sm + S_XHI + hwl * PB + c * 2) = pack_hi(v0, v1);
            *(uint32_t*)(sm + S_XLO + hwl * PB + c * 2) = pack_lo(v0, v1);
        }
        ((float*)(sm + S_XXP))[ch4 * 128 + hwl] = xxa;
    }

    // ---- w: fp32 -> bf16 hi/lo pitched; ee[k] = ||w_k||^2 -----------------
    {
        const float4* w4 = (const float4*)w;
#pragma unroll
        for (int it = 0; it < 16; ++it) {
            const int u = t + 512 * it;
            const int k = u >> 4, j = u & 15;          // 16 threads per code
            float4 v = w4[(size_t)k * 16 + j];
            float s = v.x * v.x + v.y * v.y + v.z * v.z + v.w * v.w;
            s += __shfl_xor_sync(0xffffffffu, s, 8);
            s += __shfl_xor_sync(0xffffffffu, s, 4);
            s += __shfl_xor_sync(0xffffffffu, s, 2);
            s += __shfl_xor_sync(0xffffffffu, s, 1);
            if ((t & 15) == 0) ((float*)(sm + S_EE))[k] = s;
            *(uint2*)(sm + S_WHI + k * PB + j * 8) =
                make_uint2(pack_hi(v.x, v.y), pack_hi(v.z, v.w));
            *(uint2*)(sm + S_WLO + k * PB + j * 8) =
                make_uint2(pack_lo(v.x, v.y), pack_lo(v.z, v.w));
        }
    }
    __syncthreads();

    // ---- per-warp MMA: 16 rows (wg) x 256 codes (h half) ------------------
    const int wg = wid >> 1, h = wid & 1;
    const int r0 = wg * 16;
    const int l7 = lane & 7, seg = lane >> 3, t4 = lane & 3, g = lane >> 2;

    const uint32_t aoff = (uint32_t)(r0 + l7 + ((seg & 1) << 3)) * PB + ((seg >> 1) << 4);
    uint32_t AH[4][4], AL[4][4];
#pragma unroll
    for (int kk = 0; kk < 4; ++kk) {
        LDSM_X4(AH[kk], su + S_XHI + aoff + kk * 32);
        LDSM_X4(AL[kk], su + S_XLO + aoff + kk * 32);
    }
    const uint32_t boff = (uint32_t)(l7 + ((seg >> 1) << 3)) * PB + ((seg & 1) << 4);

    const float* ee = (const float*)(sm + S_EE);
    const float* xxp = (const float*)(sm + S_XXP);
    // full-domain row norms for this thread's two rows (same sum order used
    // everywhere so values are bitwise-consistent across the kernel)
    const float xg0 = xxp[r0 + g]     + xxp[128 + r0 + g]
                    + xxp[256 + r0 + g] + xxp[384 + r0 + g];
    const float xg8 = xxp[r0 + g + 8] + xxp[128 + r0 + g + 8]
                    + xxp[256 + r0 + g + 8] + xxp[384 + r0 + g + 8];
    float* stg = (float*)(sm + S_STG) + wid * (16 * 34);

    float d1 = 3.4e38f, d2 = 3.4e38f;        // top2 over this warp's 256 cols
    int   k1 = 0, k2 = 0;                    // row g
    float d1b = 3.4e38f, d2b = 3.4e38f;      // row g+8
    int   k1b = 0, k2b = 0;

    for (int nc = 0; nc < 4; ++nc) {
        const int cbase = h * 256 + nc * 64;
        float acc[8][4];
#pragma unroll
        for (int q = 0; q < 8; ++q)
#pragma unroll
            for (int r = 0; r < 4; ++r) acc[q][r] = 0.f;

        const uint32_t wbh = su + S_WHI + cbase * PB + boff;
        const uint32_t wbl = su + S_WLO + cbase * PB + boff;
#pragma unroll
        for (int p = 0; p < 4; ++p)
#pragma unroll
            for (int kk = 0; kk < 4; ++kk) {
                uint32_t BH[4], BL[4];
                LDSM_X4(BH, wbh + p * 16 * PB + kk * 32);
                LDSM_X4(BL, wbl + p * 16 * PB + kk * 32);
                MMA16816(acc[2 * p],     AH[kk], BH);
                MMA16816(acc[2 * p + 1], AH[kk], BH + 2);
                MMA16816(acc[2 * p],     AH[kk], BL);
                MMA16816(acc[2 * p + 1], AH[kk], BL + 2);
                MMA16816(acc[2 * p],     AL[kk], BH);
                MMA16816(acc[2 * p + 1], AL[kk], BH + 2);
            }

        // two 32-col halves: stage full-domain D -> top2 -> coalesced flush
#pragma unroll
        for (int ha = 0; ha < 2; ++ha) {
#pragma unroll
            for (int ntl = 0; ntl < 4; ++ntl) {
                const int nt = ha * 4 + ntl;
                const int kloc = ntl * 8 + 2 * t4;
                const int kg = cbase + ha * 32 + kloc;
                const float2 eev = *(const float2*)(ee + kg);
                const float D0 = xg0 + eev.x - 2.f * acc[nt][0];
                const float D1 = xg0 + eev.y - 2.f * acc[nt][1];
                const float D2 = xg8 + eev.x - 2.f * acc[nt][2];
                const float D3 = xg8 + eev.y - 2.f * acc[nt][3];
                top2_upd(D0, kg,     d1, k1, d2, k2);
                top2_upd(D1, kg + 1, d1, k1, d2, k2);
                top2_upd(D2, kg,     d1b, k1b, d2b, k2b);
                top2_upd(D3, kg + 1, d1b, k1b, d2b, k2b);
                *(float2*)(stg + g * 34 + kloc)       = make_float2(D0, D1);
                *(float2*)(stg + (g + 8) * 34 + kloc) = make_float2(D2, D3);
            }
            __syncwarp();
            // flush 16 rows x 32 cols (plain copy; values already full-domain)
            {
                float* gpD = out + OFF_DIST + (size_t)(n0 + r0) * 512 + cbase + ha * 32;
#pragma unroll
                for (int row = 0; row < 16; ++row)
                    gpD[(size_t)row * 512 + lane] = stg[row * 34 + lane];
            }
            __syncwarp();
        }
    }

    // ---- per-row top2 within warp (4 lanes/row), then publish to SMEM -----
#pragma unroll
    for (int m = 1; m <= 2; m <<= 1) {
        float e1 = __shfl_xor_sync(0xffffffffu, d1, m);
        int   j1 = __shfl_xor_sync(0xffffffffu, k1, m);
        float e2 = __shfl_xor_sync(0xffffffffu, d2, m);
        int   j2 = __shfl_xor_sync(0xffffffffu, k2, m);
        top2_merge(e1, j1, e2, j2, d1, k1, d2, k2);
        e1 = __shfl_xor_sync(0xffffffffu, d1b, m);
        j1 = __shfl_xor_sync(0xffffffffu, k1b, m);
        e2 = __shfl_xor_sync(0xffffffffu, d2b, m);
        j2 = __shfl_xor_sync(0xffffffffu, k2b, m);
        top2_merge(e1, j1, e2, j2, d1b, k1b, d2b, k2b);
    }
    if (t4 == 0) {
        const int rA = r0 + g, rB = rA + 8;
        ((float*)(sm + S_CD1))[h * 128 + rA] = d1;
        ((float*)(sm + S_CD2))[h * 128 + rA] = d2;
        ((int*)  (sm + S_CK1))[h * 128 + rA] = k1;
        ((int*)  (sm + S_CK2))[h * 128 + rA] = k2;
        ((float*)(sm + S_CD1))[h * 128 + rB] = d1b;
        ((float*)(sm + S_CD2))[h * 128 + rB] = d2b;
        ((int*)  (sm + S_CK1))[h * 128 + rB] = k1b;
        ((int*)  (sm + S_CK2))[h * 128 + rB] = k2b;
    }
    __syncthreads();

    // ---- one thread per row: merge halves, exact full-domain fixup --------
    float rowmin = 0.f;
    if (t < 128) {
        const float* cd1 = (const float*)(sm + S_CD1);
        const float* cd2 = (const float*)(sm + S_CD2);
        const int*   ck1 = (const int*)(sm + S_CK1);
        const int*   ck2 = (const int*)(sm + S_CK2);
        float m1 = cd1[t], m2 = cd2[t];
        int   q1 = ck1[t], q2 = ck2[t];
        top2_merge(cd1[128 + t], ck1[128 + t], cd2[128 + t], ck2[128 + t],
                   m1, q1, m2, q2);
        const float xr2 = xxp[t] + xxp[128 + t] + xxp[256 + t] + xxp[384 + t];
        const float TAU = 1e-5f;
        if (m2 - m1 < TAU) {     // exact fp32 recompute, full domain (as ref)
            const float* xr = x + (size_t)bb * 65536 + hw0 + t;
            const float DA = xr2 + ((const float*)(sm + S_EE))[q1]
                             - 2.f * dot_exact(xr, w + (size_t)q1 * 64);
            const float DB = xr2 + ((const float*)(sm + S_EE))[q2]
                             - 2.f * dot_exact(xr, w + (size_t)q2 * 64);
            if (DB < DA || (DB == DA && q2 < q1)) { q1 = q2; m1 = DB; }
            else m1 = DA;
        }
        ((int*)(sm + S_IDX))[t] = q1;
        out[OFF_EIDX + n0 + t] = (float)q1;
        rowmin = m1;             // full-domain min distance
        atomicAdd(&g_cnt[q1], 1u);
    }

    // ---- loss partial: rows live in warps 0-3 -----------------------------
#pragma unroll
    for (int off = 16; off > 0; off >>= 1)
        rowmin += __shfl_down_sync(0xffffffffu, rowmin, off);
    if (lane == 0 && wid < 4) ((float*)(sm + S_LRED))[wid] = rowmin;
    __syncthreads();
    if (t == 0) {
        const float* lr = (const float*)(sm + S_LRED);
        const float ctaLoss = lr[0] + lr[1] + lr[2] + lr[3];
        atomicAdd(&g_loss_i[bb],
                  (unsigned long long)((double)ctaLoss * 65536.0 + 0.5));
    }

    // ---- encodings: 16 warps x 8 rows, coalesced one-hot ------------------
    {
        const int* idxs = (const int*)(sm + S_IDX);
#pragma unroll
        for (int rr = 0; rr < 8; ++rr) {
            const int row = wid * 8 + rr;
            const int ebk = idxs[row];
            float* ep = out + OFF_ENC + (size_t)(n0 + row) * 512;
#pragma unroll
            for (int i2 = 0; i2 < 16; ++i2) {
                const int col = lane + 32 * i2;
                ep[col] = (col == ebk) ? 1.f : 0.f;
            }
        }
    }

    // ---- q_out via SMEM transpose staging (reuses stage region) -----------
    __syncthreads();
    float* qs = (float*)(sm + S_STG);
    const int* idxs = (const int*)(sm + S_IDX);
    {
        const int rr = wid * 8;
#pragma unroll
        for (int q = 0; q < 8; ++q) {
            const float* wr = w + (size_t)idxs[rr + q] * 64;
            qs[(rr + q) * 66 + lane]      = wr[lane];
            qs[(rr + q) * 66 + 32 + lane] = wr[32 + lane];
        }
    }
    __syncthreads();
    float* qb = out + OFF_Q + (size_t)bb * 65536 + hw0;
#pragma unroll
    for (int i2 = 0; i2 < 16; ++i2) {
        const int u = t + 512 * i2;
        const int c = u >> 7, hl = u & 127;
        qb[(size_t)c * 1024 + hl] = qs[hl * 66 + c];
    }

    // ---- last-CTA finalize: perplexity + loss, then reset scratch ---------
    __shared__ unsigned s_last;
    __threadfence();
    __syncthreads();
    if (t == 0) s_last = (atomicAdd(&g_tick, 1u) == 511u) ? 1u : 0u;
    __syncthreads();
    if (s_last) {
        __threadfence();
        const unsigned c0 = *(volatile unsigned*)&g_cnt[t];
        const float p0 = (float)c0 * (1.f / 65536.f);
        float s = p0 * logf(p0 + 1e-10f);
#pragma unroll
        for (int off = 16; off > 0; off >>= 1) s += __shfl_down_sync(0xffffffffu, s, off);
        float* red = (float*)(sm + S_LRED);
        if (lane == 0) red[wid] = s;
        __syncthreads();
        if (t == 0) {
            float tot = 0.f;
#pragma unroll
            for (int q = 0; q < 16; ++q) tot += red[q];
            out[OFF_PERP] = expf(-tot);
        }
        if (t < 64) {
            const unsigned long long v = *(volatile unsigned long long*)&g_loss_i[t];
            out[OFF_LOSS + t] = (float)((double)v * (1.25 / (65536.0 * 65536.0)));
            g_loss_i[t] = 0ull;
        }
        g_cnt[t] = 0u;
        if (t == 0) g_tick = 0u;
    }
}

// ===========================================================================
extern "C" void kernel_launch(void* const* d_in, const int* in_sizes, int n_in,
                              void* d_out, int out_size) {
    const float* x = (const float*)d_in[0];
    const float* w = (const float*)d_in[1];
    float* out = (float*)d_out;

    cudaFuncSetAttribute(k_main, cudaFuncAttributeMaxDynamicSharedMemorySize, S_TOTAL);
    k_main<<<512, 512, S_TOTAL>>>(x, w, out);
}